// round 1
// baseline (speedup 1.0000x reference)
#include <cuda_runtime.h>
#include <math.h>

#define N      8192
#define D      256
#define NC     64          // classes (H*W)
#define KNN5   5
#define JBLK   64          // 8192 / 128 j-blocks
#define CAND   (JBLK*KNN5) // 320 candidates per row
#define NB_IT  148
#define MAXIT  100
#define LAM    1.0f

// ---------------- scratch (device globals; no runtime allocation) -----------
__device__ float g_F[N * D];          // normalized feats, row-major
__device__ float g_FT[D * N];         // transposed (k-major) for coalesced B loads
__device__ float g_unary[N * NC];
__device__ float g_Ybuf[2][N * NC];
__device__ float g_candV[N * CAND];
__device__ int   g_candI[N * CAND];
__device__ int   g_nbr[N * KNN5];
__device__ float g_partE[2][NB_IT];
__device__ unsigned          g_barCount;
__device__ volatile unsigned g_barGen;

// ---------------- helpers ---------------------------------------------------
__device__ __forceinline__ void top5_insert(float v, int j, float bv[5], int bi[5]) {
    if (v > bv[4] || (v == bv[4] && j < bi[4])) {
        bv[4] = v; bi[4] = j;
#pragma unroll
        for (int s = 4; s > 0; --s) {
            if (bv[s] > bv[s-1] || (bv[s] == bv[s-1] && bi[s] < bi[s-1])) {
                float tv = bv[s]; bv[s] = bv[s-1]; bv[s-1] = tv;
                int   tj = bi[s]; bi[s] = bi[s-1]; bi[s-1] = tj;
            }
        }
    }
}

__device__ __forceinline__ void gridBarrier() {
    __syncthreads();
    if (threadIdx.x == 0) {
        __threadfence();
        unsigned gen = g_barGen;
        if (atomicAdd(&g_barCount, 1u) == gridDim.x - 1u) {
            g_barCount = 0u;
            __threadfence();
            g_barGen = gen + 1u;           // release
        } else {
            while (g_barGen == gen) { }    // sense-reversal spin
            __threadfence();
        }
    }
    __syncthreads();
}

// ---------------- prep: unary + Y0 ------------------------------------------
// grid 1024 x 256 threads (8 warps/blk, warp per row)
__global__ void k_prep_unary(const float* __restrict__ scores) {
    int wib = threadIdx.x >> 5, lane = threadIdx.x & 31;
    int r = blockIdx.x * 8 + wib;
    const float* s = scores + (size_t)r * NC;
    float u0 = -logf(s[lane]      + 1e-10f);
    float u1 = -logf(s[lane + 32] + 1e-10f);
    g_unary[r * NC + lane]      = u0;
    g_unary[r * NC + 32 + lane] = u1;
    float x0 = -u0, x1 = -u1;
    float m = fmaxf(x0, x1);
#pragma unroll
    for (int o = 16; o > 0; o >>= 1) m = fmaxf(m, __shfl_xor_sync(0xffffffffu, m, o));
    float e0 = __expf(x0 - m), e1 = __expf(x1 - m);
    float t = e0 + e1;
#pragma unroll
    for (int o = 16; o > 0; o >>= 1) t += __shfl_xor_sync(0xffffffffu, t, o);
    float inv = 1.0f / t;
    g_Ybuf[0][r * NC + lane]      = e0 * inv;
    g_Ybuf[0][r * NC + 32 + lane] = e1 * inv;
}

// ---------------- prep: normalize feats, write F and F^T --------------------
// grid 8192 x 256 (block per row)
__global__ void k_prep_feats(const float* __restrict__ feats) {
    __shared__ float red[8];
    __shared__ float nrmsh;
    int r = blockIdx.x, k = threadIdx.x;
    int lane = k & 31, w = k >> 5;
    float v = feats[(size_t)r * D + k];
    float s = v * v;
#pragma unroll
    for (int o = 16; o > 0; o >>= 1) s += __shfl_xor_sync(0xffffffffu, s, o);
    if (lane == 0) red[w] = s;
    __syncthreads();
    if (k == 0) {
        float t = 0.f;
#pragma unroll
        for (int i = 0; i < 8; ++i) t += red[i];
        nrmsh = sqrtf(t);
    }
    __syncthreads();
    float f = v / fmaxf(nrmsh, 1e-12f);
    g_F[(size_t)r * D + k]  = f;
    g_FT[(size_t)k * N + r] = f;
}

// ---------------- Gram (F F^T) 128x128 tiles + fused partial top-5 ----------
// grid (64, 64) x 256 threads; dynamic smem = max(A+B, Cs) = 33024 B
__global__ void k_gram_topk() {
    extern __shared__ float smem[];
    float* As = smem;              // [16][128]
    float* Bs = smem + 16 * 128;   // [16][128]
    const int tid = threadIdx.x;
    const int ib = blockIdx.y * 128, jb = blockIdx.x * 128;
    const int ty = tid >> 4, tx = tid & 15;
    const int rowg = ty * 8, colg = tx * 8;

    float acc[8][8];
#pragma unroll
    for (int i = 0; i < 8; ++i)
#pragma unroll
        for (int j = 0; j < 8; ++j) acc[i][j] = 0.f;

    for (int k0 = 0; k0 < D; k0 += 16) {
#pragma unroll
        for (int l = 0; l < 2; ++l) {   // A tile: 128 rows x 16 k
            int e = tid + l * 256;
            int row = e >> 2;
            int k4 = (e & 3) * 4;
            float4 v = *(const float4*)(g_F + (size_t)(ib + row) * D + k0 + k4);
            As[(k4 + 0) * 128 + row] = v.x;
            As[(k4 + 1) * 128 + row] = v.y;
            As[(k4 + 2) * 128 + row] = v.z;
            As[(k4 + 3) * 128 + row] = v.w;
        }
#pragma unroll
        for (int l = 0; l < 2; ++l) {   // B tile: 16 k x 128 cols from F^T
            int e = tid + l * 256;
            int kk = e >> 5;
            int j4 = (e & 31) * 4;
            float4 v = *(const float4*)(g_FT + (size_t)(k0 + kk) * N + jb + j4);
            *(float4*)(Bs + kk * 128 + j4) = v;
        }
        __syncthreads();
#pragma unroll
        for (int kk = 0; kk < 16; ++kk) {
            float a[8], b[8];
            *(float4*)(a)     = *(float4*)(As + kk * 128 + rowg);
            *(float4*)(a + 4) = *(float4*)(As + kk * 128 + rowg + 4);
            *(float4*)(b)     = *(float4*)(Bs + kk * 128 + colg);
            *(float4*)(b + 4) = *(float4*)(Bs + kk * 128 + colg + 4);
#pragma unroll
            for (int i = 0; i < 8; ++i)
#pragma unroll
                for (int j = 0; j < 8; ++j)
                    acc[i][j] = fmaf(a[i], b[j], acc[i][j]);
        }
        __syncthreads();
    }

    // epilogue: two half-tiles through smem, per-row top-5 scan
    float* Cs = smem;  // [64][129]
#pragma unroll
    for (int pass = 0; pass < 2; ++pass) {
        if ((rowg >> 6) == pass) {
            int r0 = rowg & 63;
#pragma unroll
            for (int i = 0; i < 8; ++i)
#pragma unroll
                for (int j = 0; j < 8; ++j)
                    Cs[(r0 + i) * 129 + colg + j] = acc[i][j];
        }
        __syncthreads();
        if (tid < 64) {
            int gi = ib + pass * 64 + tid;
            float bv[5]; int bi[5];
#pragma unroll
            for (int s = 0; s < 5; ++s) { bv[s] = -__int_as_float(0x7f800000); bi[s] = 0x7fffffff; }
            for (int c = 0; c < 128; ++c) {
                int gj = jb + c;
                if (gj == gi) continue;
                top5_insert(Cs[tid * 129 + c], gj, bv, bi);
            }
            size_t base = (size_t)gi * CAND + (size_t)blockIdx.x * KNN5;
#pragma unroll
            for (int s = 0; s < 5; ++s) { g_candV[base + s] = bv[s]; g_candI[base + s] = bi[s]; }
        }
        __syncthreads();
    }
}

// ---------------- merge 64 partial top-5 lists -> final 5-NN ----------------
// grid 32 x 256 (thread per row)
__global__ void k_merge() {
    int r = blockIdx.x * 256 + threadIdx.x;
    if (r >= N) return;
    float bv[5]; int bi[5];
#pragma unroll
    for (int s = 0; s < 5; ++s) { bv[s] = -__int_as_float(0x7f800000); bi[s] = 0x7fffffff; }
    size_t base = (size_t)r * CAND;
    for (int c = 0; c < CAND; ++c)
        top5_insert(g_candV[base + c], g_candI[base + c], bv, bi);
#pragma unroll
    for (int s = 0; s < 5; ++s) g_nbr[r * KNN5 + s] = bi[s];
}

// ---------------- persistent mean-field iteration ---------------------------
// grid NB_IT x 256 (all blocks co-resident; hand-rolled grid barrier)
__global__ void k_iterate(float* __restrict__ dout) {
    __shared__ float sE[8];
    const int tid  = threadIdx.x;
    const int lane = tid & 31, wib = tid >> 5;
    const int warpG = blockIdx.x * 8 + wib;
    const int nW = gridDim.x * 8;
    float Eprev = __int_as_float(0x7f800000);

    for (int it = 0; it < MAXIT; ++it) {
        const float* __restrict__ Yin  = g_Ybuf[it & 1];
        float* __restrict__ Yout = g_Ybuf[(it + 1) & 1];
        float myE = 0.f;
        for (int r = warpG; r < N; r += nW) {
            const int* nb = g_nbr + r * KNN5;
            float pw0 = 0.f, pw1 = 0.f;
#pragma unroll
            for (int n = 0; n < KNN5; ++n) {
                const float* yr = Yin + (size_t)nb[n] * NC;
                pw0 += yr[lane];
                pw1 += yr[lane + 32];
            }
            pw0 *= LAM; pw1 *= LAM;
            float u0 = g_unary[r * NC + lane], u1 = g_unary[r * NC + 32 + lane];
            float x0 = pw0 - u0, x1 = pw1 - u1;
            float m = fmaxf(x0, x1);
#pragma unroll
            for (int o = 16; o > 0; o >>= 1) m = fmaxf(m, __shfl_xor_sync(0xffffffffu, m, o));
            float e0 = __expf(x0 - m), e1 = __expf(x1 - m);
            float s = e0 + e1;
#pragma unroll
            for (int o = 16; o > 0; o >>= 1) s += __shfl_xor_sync(0xffffffffu, s, o);
            float inv = 1.0f / s;
            float y0 = e0 * inv, y1 = e1 * inv;
            Yout[r * NC + lane]      = y0;
            Yout[r * NC + 32 + lane] = y1;
            dout[r * NC + lane]      = y0;
            dout[r * NC + 32 + lane] = y1;
            float ls = __logf(s);
            // E += u*y - LAM*pw*y + y*log(y);  log(y) = (x-m) - log(s)
            myE += y0 * (u0 - LAM * pw0 + (x0 - m - ls))
                 + y1 * (u1 - LAM * pw1 + (x1 - m - ls));
        }
        // deterministic reduction: warp -> block -> global partial
#pragma unroll
        for (int o = 16; o > 0; o >>= 1) myE += __shfl_xor_sync(0xffffffffu, myE, o);
        if (lane == 0) sE[wib] = myE;
        __syncthreads();
        if (tid == 0) {
            float e = 0.f;
#pragma unroll
            for (int w = 0; w < 8; ++w) e += sE[w];
            g_partE[it & 1][blockIdx.x] = e;
        }
        gridBarrier();
        float E = 0.f;
        for (int b = 0; b < NB_IT; ++b) E += g_partE[it & 1][b];
        bool conv = (it > 1) && (fabsf(E - Eprev) <= 1e-8f * fabsf(Eprev));
        Eprev = E;
        if (conv) break;
    }
}

// ---------------- launch -----------------------------------------------------
extern "C" void kernel_launch(void* const* d_in, const int* in_sizes, int n_in,
                              void* d_out, int out_size) {
    const float* scores;
    const float* feats;
    if (in_sizes[0] == N * NC) { scores = (const float*)d_in[0]; feats = (const float*)d_in[1]; }
    else                       { scores = (const float*)d_in[1]; feats = (const float*)d_in[0]; }
    float* out = (float*)d_out;

    k_prep_unary<<<N / 8, 256>>>(scores);
    k_prep_feats<<<N, 256>>>(feats);

    const int gram_smem = 64 * 129 * sizeof(float);   // 33024 B (>= A+B tiles)
    dim3 gg(JBLK, JBLK);
    k_gram_topk<<<gg, 256, gram_smem>>>();

    k_merge<<<N / 256, 256>>>();
    k_iterate<<<NB_IT, 256>>>(out);
}

// round 4
// speedup vs baseline: 1.9693x; 1.9693x over previous
#include <cuda_runtime.h>
#include <cuda_bf16.h>
#include <math.h>
#include <stdint.h>

#define N      8192
#define D      256
#define NC     64
#define KNN5   5
#define TI     128
#define KD     768          // split-bf16 expanded K: [h,l,h] x [h,h,l]
#define KC     64           // bf16 per smem stage (128 B/row)
#define NSTG   (KD/KC)      // 12
#define NBI    (N/TI)       // 64 block-rows
#define CAND   (NBI*KNN5)   // 320 candidates per row
#define NB_IT  148
#define MAXIT  100
#define LAM    1.0f

// ---------------- scratch ----------------------------------------------------
__device__ __nv_bfloat16 g_A[(size_t)N * KD];   // [h, l, h]
__device__ __nv_bfloat16 g_B[(size_t)N * KD];   // [h, h, l]
__device__ float g_unary[N * NC];
__device__ float g_Ybuf[2][N * NC];
__device__ float g_candV[(size_t)CAND * N];     // transposed: [slot][row]
__device__ int   g_candI[(size_t)CAND * N];
__device__ int   g_nbr[N * KNN5];
__device__ float g_partE[2][NB_IT];
__device__ unsigned          g_barCount;
__device__ volatile unsigned g_barGen;

// ---------------- PTX helpers ------------------------------------------------
__device__ __forceinline__ uint32_t smem_u32(const void* p) {
    uint32_t a;
    asm("{ .reg .u64 t; cvta.to.shared.u64 t, %1; cvt.u32.u64 %0, t; }" : "=r"(a) : "l"(p));
    return a;
}
#define SWZ128(o) ((o) ^ (((o) >> 3) & 0x70))
#define CP_ASYNC16(dst, src) \
    asm volatile("cp.async.cg.shared.global [%0], [%1], 16;" :: "r"(dst), "l"(src) : "memory")
#define CP_COMMIT() asm volatile("cp.async.commit_group;" ::: "memory")
#define CP_WAIT(n)  asm volatile("cp.async.wait_group %0;" :: "n"(n) : "memory")
#define LDSM_X4(r0,r1,r2,r3, a) \
    asm volatile("ldmatrix.sync.aligned.m8n8.x4.shared.b16 {%0,%1,%2,%3}, [%4];" \
        : "=r"(r0),"=r"(r1),"=r"(r2),"=r"(r3) : "r"(a))
#define LDSM_X2(r0,r1, a) \
    asm volatile("ldmatrix.sync.aligned.m8n8.x2.shared.b16 {%0,%1}, [%2];" \
        : "=r"(r0),"=r"(r1) : "r"(a))
#define MMA16816(d, a, b) \
    asm volatile("mma.sync.aligned.m16n8k16.row.col.f32.bf16.bf16.f32 " \
        "{%0,%1,%2,%3}, {%4,%5,%6,%7}, {%8,%9}, {%0,%1,%2,%3};" \
        : "+f"((d)[0]),"+f"((d)[1]),"+f"((d)[2]),"+f"((d)[3]) \
        : "r"((a)[0]),"r"((a)[1]),"r"((a)[2]),"r"((a)[3]), "r"((b)[0]),"r"((b)[1]))

// ---------------- misc helpers ----------------------------------------------
__device__ __forceinline__ void top5_insert(float v, int j, float bv[5], int bi[5]) {
    if (v > bv[4] || (v == bv[4] && j < bi[4])) {
        bv[4] = v; bi[4] = j;
#pragma unroll
        for (int s = 4; s > 0; --s) {
            if (bv[s] > bv[s-1] || (bv[s] == bv[s-1] && bi[s] < bi[s-1])) {
                float tv = bv[s]; bv[s] = bv[s-1]; bv[s-1] = tv;
                int   tj = bi[s]; bi[s] = bi[s-1]; bi[s-1] = tj;
            }
        }
    }
}
__device__ __forceinline__ void gridBarrier() {
    __syncthreads();
    if (threadIdx.x == 0) {
        __threadfence();
        unsigned gen = g_barGen;
        if (atomicAdd(&g_barCount, 1u) == gridDim.x - 1u) {
            g_barCount = 0u;
            __threadfence();
            g_barGen = gen + 1u;
        } else {
            while (g_barGen == gen) { }
            __threadfence();
        }
    }
    __syncthreads();
}

// ---------------- prep: unary + Y0 ------------------------------------------
__global__ void k_prep_unary(const float* __restrict__ scores) {
    int wib = threadIdx.x >> 5, lane = threadIdx.x & 31;
    int r = blockIdx.x * 8 + wib;
    const float* s = scores + (size_t)r * NC;
    float u0 = -logf(s[lane]      + 1e-10f);
    float u1 = -logf(s[lane + 32] + 1e-10f);
    g_unary[r * NC + lane]      = u0;
    g_unary[r * NC + 32 + lane] = u1;
    float x0 = -u0, x1 = -u1;
    float m = fmaxf(x0, x1);
#pragma unroll
    for (int o = 16; o > 0; o >>= 1) m = fmaxf(m, __shfl_xor_sync(0xffffffffu, m, o));
    float e0 = __expf(x0 - m), e1 = __expf(x1 - m);
    float t = e0 + e1;
#pragma unroll
    for (int o = 16; o > 0; o >>= 1) t += __shfl_xor_sync(0xffffffffu, t, o);
    float inv = 1.0f / t;
    g_Ybuf[0][r * NC + lane]      = e0 * inv;
    g_Ybuf[0][r * NC + 32 + lane] = e1 * inv;
}

// ---------------- prep: normalize + split into bf16 hi/lo --------------------
__global__ void k_prep_feats(const float* __restrict__ feats) {
    __shared__ float red[8];
    __shared__ float nrmsh;
    int r = blockIdx.x, k = threadIdx.x;
    int lane = k & 31, w = k >> 5;
    float v = feats[(size_t)r * D + k];
    float s = v * v;
#pragma unroll
    for (int o = 16; o > 0; o >>= 1) s += __shfl_xor_sync(0xffffffffu, s, o);
    if (lane == 0) red[w] = s;
    __syncthreads();
    if (k == 0) {
        float t = 0.f;
#pragma unroll
        for (int i = 0; i < 8; ++i) t += red[i];
        nrmsh = sqrtf(t);
    }
    __syncthreads();
    float f = v / fmaxf(nrmsh, 1e-12f);
    __nv_bfloat16 h = __float2bfloat16(f);
    __nv_bfloat16 l = __float2bfloat16(f - __bfloat162float(h));
    size_t base = (size_t)r * KD;
    g_A[base + k]       = h;
    g_A[base + 256 + k] = l;
    g_A[base + 512 + k] = h;
    g_B[base + k]       = h;
    g_B[base + 256 + k] = h;
    g_B[base + 512 + k] = l;
}

// ---------------- HMMA Gram, upper-triangle tiles, fused dual top-5 ----------
// grid 2080 x 256 threads; dynamic smem = 64 KB
// buffers: A0 @0, A1 @16K, B0 @32K, B1 @48K (16 KB each = 128 rows x 128 B)
__global__ void __launch_bounds__(256) k_gram_mma() {
    extern __shared__ char smem[];
    float* Cs = (float*)smem;                 // [64][129] overlay for epilogue
    const uint32_t sb = smem_u32(smem);
    const int tid = threadIdx.x;
    const int lane = tid & 31, warp = tid >> 5;
    const int wm = warp >> 2, wn = warp & 3;  // 2 x 4 warp grid

    // linear -> upper-triangle (bi, bj)
    int bi = 0, rem = blockIdx.x;
    while (rem >= NBI - bi) { rem -= NBI - bi; ++bi; }
    const int bj = bi + rem;
    const int ib = bi * TI, jb = bj * TI;

    float acc[4][4][4];
#pragma unroll
    for (int mf = 0; mf < 4; ++mf)
#pragma unroll
        for (int nf = 0; nf < 4; ++nf)
#pragma unroll
            for (int q = 0; q < 4; ++q) acc[mf][nf][q] = 0.f;

    const char* gA = (const char*)g_A;
    const char* gB = (const char*)g_B;

    // cp.async stage loader: 128 rows x 8 chunks(16B) per matrix -> 4 chunks/thread each
#define LOAD_STAGE(sidx, buf) do {                                              \
        int _s = (sidx); uint32_t _b = (uint32_t)(buf);                         \
        _Pragma("unroll")                                                       \
        for (int t = 0; t < 4; ++t) {                                           \
            int e = tid + t * 256;                                              \
            int row = e >> 3, ch = e & 7;                                       \
            uint32_t off = SWZ128((uint32_t)(row * 128 + ch * 16));             \
            CP_ASYNC16(sb + _b * 16384u + off,                                  \
                gA + ((size_t)(ib + row) * KD + (size_t)_s * KC) * 2 + ch * 16);\
            CP_ASYNC16(sb + 32768u + _b * 16384u + off,                         \
                gB + ((size_t)(jb + row) * KD + (size_t)_s * KC) * 2 + ch * 16);\
        }                                                                       \
        CP_COMMIT();                                                            \
    } while (0)

    LOAD_STAGE(0, 0);

    for (int s = 0; s < NSTG; ++s) {
        if (s + 1 < NSTG) { LOAD_STAGE(s + 1, (s + 1) & 1); CP_WAIT(1); }
        else              { CP_WAIT(0); }
        __syncthreads();

        const uint32_t aS = sb + (uint32_t)(s & 1) * 16384u;
        const uint32_t bS = sb + 32768u + (uint32_t)(s & 1) * 16384u;
#pragma unroll
        for (int kk = 0; kk < 4; ++kk) {
            uint32_t a[4][4], b[4][2];
#pragma unroll
            for (int mf = 0; mf < 4; ++mf) {
                int row = wm * 64 + mf * 16 + (lane & 15);
                uint32_t kb = kk * 32 + ((lane >> 4) << 4);
                LDSM_X4(a[mf][0], a[mf][1], a[mf][2], a[mf][3], aS + SWZ128((uint32_t)(row * 128) + kb));
            }
#pragma unroll
            for (int nf = 0; nf < 4; ++nf) {
                int nrow = wn * 32 + nf * 8 + (lane & 7);
                uint32_t kb = kk * 32 + (((lane >> 3) & 1) << 4);
                LDSM_X2(b[nf][0], b[nf][1], bS + SWZ128((uint32_t)(nrow * 128) + kb));
            }
#pragma unroll
            for (int mf = 0; mf < 4; ++mf)
#pragma unroll
                for (int nf = 0; nf < 4; ++nf)
                    MMA16816(acc[mf][nf], a[mf], b[nf]);
        }
        __syncthreads();   // all reads of this buffer done before next prefetch lands
    }

    // epilogue: two 64x128 halves through smem; row top-5 (i side), col top-5 (j side)
    float bvC[5]; int biC[5];
#pragma unroll
    for (int q = 0; q < 5; ++q) { bvC[q] = -__int_as_float(0x7f800000); biC[q] = 0x7fffffff; }

#pragma unroll
    for (int h = 0; h < 2; ++h) {
        __syncthreads();
        if (wm == h) {
#pragma unroll
            for (int mf = 0; mf < 4; ++mf)
#pragma unroll
                for (int nf = 0; nf < 4; ++nf) {
                    int r0 = mf * 16 + (lane >> 2);
                    int c0 = wn * 32 + nf * 8 + 2 * (lane & 3);
                    Cs[r0 * 129 + c0]           = acc[mf][nf][0];
                    Cs[r0 * 129 + c0 + 1]       = acc[mf][nf][1];
                    Cs[(r0 + 8) * 129 + c0]     = acc[mf][nf][2];
                    Cs[(r0 + 8) * 129 + c0 + 1] = acc[mf][nf][3];
                }
        }
        __syncthreads();
        if (tid < 64) {                       // i-side rows, slot bj
            int gi = ib + h * 64 + tid;
            float bv[5]; int bx[5];
#pragma unroll
            for (int q = 0; q < 5; ++q) { bv[q] = -__int_as_float(0x7f800000); bx[q] = 0x7fffffff; }
            for (int c = 0; c < TI; ++c) {
                int gj = jb + c;
                if (gj != gi) top5_insert(Cs[tid * 129 + c], gj, bv, bx);
            }
#pragma unroll
            for (int q = 0; q < 5; ++q) {
                g_candV[(size_t)(bj * KNN5 + q) * N + gi] = bv[q];
                g_candI[(size_t)(bj * KNN5 + q) * N + gi] = bx[q];
            }
        }
        if (bi != bj && tid < 128) {          // j-side cols, accumulate over halves
            for (int r = 0; r < 64; ++r)
                top5_insert(Cs[r * 129 + tid], ib + h * 64 + r, bvC, biC);
        }
    }
    if (bi != bj && tid < 128) {
        int gj = jb + tid;
#pragma unroll
        for (int q = 0; q < 5; ++q) {
            g_candV[(size_t)(bi * KNN5 + q) * N + gj] = bvC[q];
            g_candI[(size_t)(bi * KNN5 + q) * N + gj] = biC[q];
        }
    }
#undef LOAD_STAGE
}

// ---------------- merge 64 partial top-5 lists (coalesced) -------------------
__global__ void k_merge() {
    int rr = blockIdx.x * 256 + threadIdx.x;
    float bv[5]; int bx[5];
#pragma unroll
    for (int s = 0; s < 5; ++s) { bv[s] = -__int_as_float(0x7f800000); bx[s] = 0x7fffffff; }
    for (int c = 0; c < CAND; ++c)
        top5_insert(g_candV[(size_t)c * N + rr], g_candI[(size_t)c * N + rr], bv, bx);
#pragma unroll
    for (int s = 0; s < 5; ++s) g_nbr[rr * KNN5 + s] = bx[s] < N ? bx[s] : 0;
}

// ---------------- persistent mean-field iteration ---------------------------
__global__ void k_iterate(float* __restrict__ dout) {
    __shared__ float sE[8];
    const int tid  = threadIdx.x;
    const int lane = tid & 31, wib = tid >> 5;
    const int warpG = blockIdx.x * 8 + wib;
    const int nW = gridDim.x * 8;
    float Eprev = __int_as_float(0x7f800000);
    int finalBuf = -1;

    for (int it = 0; it < MAXIT; ++it) {
        const float* __restrict__ Yin  = g_Ybuf[it & 1];
        float* __restrict__ Yout = g_Ybuf[(it + 1) & 1];
        float myE = 0.f;
        for (int rr = warpG; rr < N; rr += nW) {
            const int* nb = g_nbr + rr * KNN5;
            float pw0 = 0.f, pw1 = 0.f;
#pragma unroll
            for (int n = 0; n < KNN5; ++n) {
                const float* yr = Yin + (size_t)nb[n] * NC;
                pw0 += yr[lane];
                pw1 += yr[lane + 32];
            }
            pw0 *= LAM; pw1 *= LAM;
            float u0 = g_unary[rr * NC + lane], u1 = g_unary[rr * NC + 32 + lane];
            float x0 = pw0 - u0, x1 = pw1 - u1;
            float m = fmaxf(x0, x1);
#pragma unroll
            for (int o = 16; o > 0; o >>= 1) m = fmaxf(m, __shfl_xor_sync(0xffffffffu, m, o));
            float e0 = __expf(x0 - m), e1 = __expf(x1 - m);
            float s = e0 + e1;
#pragma unroll
            for (int o = 16; o > 0; o >>= 1) s += __shfl_xor_sync(0xffffffffu, s, o);
            float inv = 1.0f / s;
            float y0 = e0 * inv, y1 = e1 * inv;
            Yout[rr * NC + lane]      = y0;
            Yout[rr * NC + 32 + lane] = y1;
            float ls = __logf(s);
            myE += y0 * (u0 - LAM * pw0 + (x0 - m - ls))
                 + y1 * (u1 - LAM * pw1 + (x1 - m - ls));
        }
#pragma unroll
        for (int o = 16; o > 0; o >>= 1) myE += __shfl_xor_sync(0xffffffffu, myE, o);
        if (lane == 0) sE[wib] = myE;
        __syncthreads();
        if (tid == 0) {
            float e = 0.f;
#pragma unroll
            for (int w = 0; w < 8; ++w) e += sE[w];
            g_partE[it & 1][blockIdx.x] = e;
        }
        gridBarrier();
        float E = 0.f;
        for (int b = 0; b < NB_IT; ++b) E += g_partE[it & 1][b];
        bool conv = (it > 1) && (fabsf(E - Eprev) <= 1e-8f * fabsf(Eprev));
        Eprev = E;
        if (conv) { finalBuf = (it + 1) & 1; break; }
    }
    if (finalBuf < 0) finalBuf = MAXIT & 1;
    const float* __restrict__ Yf = g_Ybuf[finalBuf];
    for (int rr = warpG; rr < N; rr += nW) {
        dout[rr * NC + lane]      = Yf[rr * NC + lane];
        dout[rr * NC + 32 + lane] = Yf[rr * NC + 32 + lane];
    }
}

// ---------------- launch -----------------------------------------------------
extern "C" void kernel_launch(void* const* d_in, const int* in_sizes, int n_in,
                              void* d_out, int out_size) {
    const float* scores;
    const float* feats;
    if (in_sizes[0] == N * NC) { scores = (const float*)d_in[0]; feats = (const float*)d_in[1]; }
    else                       { scores = (const float*)d_in[1]; feats = (const float*)d_in[0]; }
    float* out = (float*)d_out;

    const int gram_smem = 65536;
    cudaFuncSetAttribute(k_gram_mma, cudaFuncAttributeMaxDynamicSharedMemorySize, gram_smem);

    k_prep_unary<<<N / 8, 256>>>(scores);
    k_prep_feats<<<N, 256>>>(feats);
    k_gram_mma<<<NBI * (NBI + 1) / 2, 256, gram_smem>>>();
    k_merge<<<N / 256, 256>>>();
    k_iterate<<<NB_IT, 256>>>(out);
}

// round 5
// speedup vs baseline: 2.2386x; 1.1368x over previous
#include <cuda_runtime.h>
#include <cuda_bf16.h>
#include <math.h>
#include <stdint.h>

#define N      8192
#define D      256
#define NC     64
#define KNN5   5
#define TI     128
#define KD     768          // split-bf16 expanded K: [h,l,h] x [h,h,l]
#define KC     64           // bf16 per smem stage (128 B/row)
#define NSTG   (KD/KC)      // 12
#define NBI    (N/TI)       // 64 block-rows
#define CAND   (NBI*KNN5)   // 320 candidates per row
#define NB_IT  148
#define IT_THREADS 512
#define IT_WARPS   16
#define ROWS_MAX   4        // ceil(8192 / (148*16)) = 4
#define MAXIT  100
#define LAM    1.0f

// ---------------- scratch ----------------------------------------------------
__device__ __nv_bfloat16 g_A[(size_t)N * KD];   // [h, l, h]
__device__ __nv_bfloat16 g_B[(size_t)N * KD];   // [h, h, l]
__device__ float g_unary[N * NC];
__device__ float g_Ybuf[2][N * NC];
__device__ float g_candV[(size_t)CAND * N];     // transposed: [slot][row]
__device__ int   g_candI[(size_t)CAND * N];
__device__ int   g_nbr[N * KNN5];
__device__ float g_partE[2][NB_IT];
__device__ unsigned          g_barCount;
__device__ volatile unsigned g_barGen;

// ---------------- PTX helpers ------------------------------------------------
__device__ __forceinline__ uint32_t smem_u32(const void* p) {
    uint32_t a;
    asm("{ .reg .u64 t; cvta.to.shared.u64 t, %1; cvt.u32.u64 %0, t; }" : "=r"(a) : "l"(p));
    return a;
}
#define SWZ128(o) ((o) ^ (((o) >> 3) & 0x70))
#define CP_ASYNC16(dst, src) \
    asm volatile("cp.async.cg.shared.global [%0], [%1], 16;" :: "r"(dst), "l"(src) : "memory")
#define CP_COMMIT() asm volatile("cp.async.commit_group;" ::: "memory")
#define CP_WAIT(n)  asm volatile("cp.async.wait_group %0;" :: "n"(n) : "memory")
#define LDSM_X4(r0,r1,r2,r3, a) \
    asm volatile("ldmatrix.sync.aligned.m8n8.x4.shared.b16 {%0,%1,%2,%3}, [%4];" \
        : "=r"(r0),"=r"(r1),"=r"(r2),"=r"(r3) : "r"(a))
#define LDSM_X2(r0,r1, a) \
    asm volatile("ldmatrix.sync.aligned.m8n8.x2.shared.b16 {%0,%1}, [%2];" \
        : "=r"(r0),"=r"(r1) : "r"(a))
#define MMA16816(d, a, b) \
    asm volatile("mma.sync.aligned.m16n8k16.row.col.f32.bf16.bf16.f32 " \
        "{%0,%1,%2,%3}, {%4,%5,%6,%7}, {%8,%9}, {%0,%1,%2,%3};" \
        : "+f"((d)[0]),"+f"((d)[1]),"+f"((d)[2]),"+f"((d)[3]) \
        : "r"((a)[0]),"r"((a)[1]),"r"((a)[2]),"r"((a)[3]), "r"((b)[0]),"r"((b)[1]))

// ---------------- misc helpers ----------------------------------------------
__device__ __forceinline__ void top5_insert(float v, int j, float bv[5], int bi[5]) {
    if (v > bv[4] || (v == bv[4] && j < bi[4])) {
        bv[4] = v; bi[4] = j;
#pragma unroll
        for (int s = 4; s > 0; --s) {
            if (bv[s] > bv[s-1] || (bv[s] == bv[s-1] && bi[s] < bi[s-1])) {
                float tv = bv[s]; bv[s] = bv[s-1]; bv[s-1] = tv;
                int   tj = bi[s]; bi[s] = bi[s-1]; bi[s-1] = tj;
            }
        }
    }
}
__device__ __forceinline__ void gridBarrier() {
    __syncthreads();
    if (threadIdx.x == 0) {
        __threadfence();
        unsigned gen = g_barGen;
        if (atomicAdd(&g_barCount, 1u) == gridDim.x - 1u) {
            g_barCount = 0u;
            __threadfence();
            g_barGen = gen + 1u;
        } else {
            while (g_barGen == gen) { }
            __threadfence();
        }
    }
    __syncthreads();
}

// ---------------- prep: unary + Y0 ------------------------------------------
__global__ void k_prep_unary(const float* __restrict__ scores) {
    int wib = threadIdx.x >> 5, lane = threadIdx.x & 31;
    int r = blockIdx.x * 8 + wib;
    const float* s = scores + (size_t)r * NC;
    float u0 = -logf(s[lane]      + 1e-10f);
    float u1 = -logf(s[lane + 32] + 1e-10f);
    g_unary[r * NC + lane]      = u0;
    g_unary[r * NC + 32 + lane] = u1;
    float x0 = -u0, x1 = -u1;
    float m = fmaxf(x0, x1);
#pragma unroll
    for (int o = 16; o > 0; o >>= 1) m = fmaxf(m, __shfl_xor_sync(0xffffffffu, m, o));
    float e0 = __expf(x0 - m), e1 = __expf(x1 - m);
    float t = e0 + e1;
#pragma unroll
    for (int o = 16; o > 0; o >>= 1) t += __shfl_xor_sync(0xffffffffu, t, o);
    float inv = 1.0f / t;
    g_Ybuf[0][r * NC + lane]      = e0 * inv;
    g_Ybuf[0][r * NC + 32 + lane] = e1 * inv;
}

// ---------------- prep: normalize + split into bf16 hi/lo --------------------
__global__ void k_prep_feats(const float* __restrict__ feats) {
    __shared__ float red[8];
    __shared__ float nrmsh;
    int r = blockIdx.x, k = threadIdx.x;
    int lane = k & 31, w = k >> 5;
    float v = feats[(size_t)r * D + k];
    float s = v * v;
#pragma unroll
    for (int o = 16; o > 0; o >>= 1) s += __shfl_xor_sync(0xffffffffu, s, o);
    if (lane == 0) red[w] = s;
    __syncthreads();
    if (k == 0) {
        float t = 0.f;
#pragma unroll
        for (int i = 0; i < 8; ++i) t += red[i];
        nrmsh = sqrtf(t);
    }
    __syncthreads();
    float f = v / fmaxf(nrmsh, 1e-12f);
    __nv_bfloat16 h = __float2bfloat16(f);
    __nv_bfloat16 l = __float2bfloat16(f - __bfloat162float(h));
    size_t base = (size_t)r * KD;
    g_A[base + k]       = h;
    g_A[base + 256 + k] = l;
    g_A[base + 512 + k] = h;
    g_B[base + k]       = h;
    g_B[base + 256 + k] = h;
    g_B[base + 512 + k] = l;
}

// ---------------- HMMA Gram, upper-triangle tiles, fused dual top-5 ----------
__global__ void __launch_bounds__(256) k_gram_mma() {
    extern __shared__ char smem[];
    float* Cs = (float*)smem;                 // [64][129] overlay for epilogue
    const uint32_t sb = smem_u32(smem);
    const int tid = threadIdx.x;
    const int lane = tid & 31, warp = tid >> 5;
    const int wm = warp >> 2, wn = warp & 3;  // 2 x 4 warp grid

    int bi = 0, rem = blockIdx.x;
    while (rem >= NBI - bi) { rem -= NBI - bi; ++bi; }
    const int bj = bi + rem;
    const int ib = bi * TI, jb = bj * TI;

    float acc[4][4][4];
#pragma unroll
    for (int mf = 0; mf < 4; ++mf)
#pragma unroll
        for (int nf = 0; nf < 4; ++nf)
#pragma unroll
            for (int q = 0; q < 4; ++q) acc[mf][nf][q] = 0.f;

    const char* gA = (const char*)g_A;
    const char* gB = (const char*)g_B;

#define LOAD_STAGE(sidx, buf) do {                                              \
        int _s = (sidx); uint32_t _b = (uint32_t)(buf);                         \
        _Pragma("unroll")                                                       \
        for (int t = 0; t < 4; ++t) {                                           \
            int e = tid + t * 256;                                              \
            int row = e >> 3, ch = e & 7;                                       \
            uint32_t off = SWZ128((uint32_t)(row * 128 + ch * 16));             \
            CP_ASYNC16(sb + _b * 16384u + off,                                  \
                gA + ((size_t)(ib + row) * KD + (size_t)_s * KC) * 2 + ch * 16);\
            CP_ASYNC16(sb + 32768u + _b * 16384u + off,                         \
                gB + ((size_t)(jb + row) * KD + (size_t)_s * KC) * 2 + ch * 16);\
        }                                                                       \
        CP_COMMIT();                                                            \
    } while (0)

    LOAD_STAGE(0, 0);

    for (int s = 0; s < NSTG; ++s) {
        if (s + 1 < NSTG) { LOAD_STAGE(s + 1, (s + 1) & 1); CP_WAIT(1); }
        else              { CP_WAIT(0); }
        __syncthreads();

        const uint32_t aS = sb + (uint32_t)(s & 1) * 16384u;
        const uint32_t bS = sb + 32768u + (uint32_t)(s & 1) * 16384u;
#pragma unroll
        for (int kk = 0; kk < 4; ++kk) {
            uint32_t a[4][4], b[4][2];
#pragma unroll
            for (int mf = 0; mf < 4; ++mf) {
                int row = wm * 64 + mf * 16 + (lane & 15);
                uint32_t kb = kk * 32 + ((lane >> 4) << 4);
                LDSM_X4(a[mf][0], a[mf][1], a[mf][2], a[mf][3], aS + SWZ128((uint32_t)(row * 128) + kb));
            }
#pragma unroll
            for (int nf = 0; nf < 4; ++nf) {
                int nrow = wn * 32 + nf * 8 + (lane & 7);
                uint32_t kb = kk * 32 + (((lane >> 3) & 1) << 4);
                LDSM_X2(b[nf][0], b[nf][1], bS + SWZ128((uint32_t)(nrow * 128) + kb));
            }
#pragma unroll
            for (int mf = 0; mf < 4; ++mf)
#pragma unroll
                for (int nf = 0; nf < 4; ++nf)
                    MMA16816(acc[mf][nf], a[mf], b[nf]);
        }
        __syncthreads();
    }

    float bvC[5]; int biC[5];
#pragma unroll
    for (int q = 0; q < 5; ++q) { bvC[q] = -__int_as_float(0x7f800000); biC[q] = 0x7fffffff; }

#pragma unroll
    for (int h = 0; h < 2; ++h) {
        __syncthreads();
        if (wm == h) {
#pragma unroll
            for (int mf = 0; mf < 4; ++mf)
#pragma unroll
                for (int nf = 0; nf < 4; ++nf) {
                    int r0 = mf * 16 + (lane >> 2);
                    int c0 = wn * 32 + nf * 8 + 2 * (lane & 3);
                    Cs[r0 * 129 + c0]           = acc[mf][nf][0];
                    Cs[r0 * 129 + c0 + 1]       = acc[mf][nf][1];
                    Cs[(r0 + 8) * 129 + c0]     = acc[mf][nf][2];
                    Cs[(r0 + 8) * 129 + c0 + 1] = acc[mf][nf][3];
                }
        }
        __syncthreads();
        if (tid < 64) {
            int gi = ib + h * 64 + tid;
            float bv[5]; int bx[5];
#pragma unroll
            for (int q = 0; q < 5; ++q) { bv[q] = -__int_as_float(0x7f800000); bx[q] = 0x7fffffff; }
            for (int c = 0; c < TI; ++c) {
                int gj = jb + c;
                if (gj != gi) top5_insert(Cs[tid * 129 + c], gj, bv, bx);
            }
#pragma unroll
            for (int q = 0; q < 5; ++q) {
                g_candV[(size_t)(bj * KNN5 + q) * N + gi] = bv[q];
                g_candI[(size_t)(bj * KNN5 + q) * N + gi] = bx[q];
            }
        }
        if (bi != bj && tid < 128) {
            for (int r = 0; r < 64; ++r)
                top5_insert(Cs[r * 129 + tid], ib + h * 64 + r, bvC, biC);
        }
    }
    if (bi != bj && tid < 128) {
        int gj = jb + tid;
#pragma unroll
        for (int q = 0; q < 5; ++q) {
            g_candV[(size_t)(bi * KNN5 + q) * N + gj] = bvC[q];
            g_candI[(size_t)(bi * KNN5 + q) * N + gj] = biC[q];
        }
    }
#undef LOAD_STAGE
}

// ---------------- merge: 256 blocks, warp w scans slot group w for 32 rows ---
__global__ void __launch_bounds__(256) k_merge() {
    __shared__ float sv[8][32][5];
    __shared__ int   si[8][32][5];
    const int warp = threadIdx.x >> 5, lane = threadIdx.x & 31;
    const int row = blockIdx.x * 32 + lane;

    float bv[5]; int bx[5];
#pragma unroll
    for (int q = 0; q < 5; ++q) { bv[q] = -__int_as_float(0x7f800000); bx[q] = 0x7fffffff; }
    const int c0 = warp * (CAND / 8);
    for (int c = c0; c < c0 + CAND / 8; ++c)
        top5_insert(g_candV[(size_t)c * N + row], g_candI[(size_t)c * N + row], bv, bx);
#pragma unroll
    for (int q = 0; q < 5; ++q) { sv[warp][lane][q] = bv[q]; si[warp][lane][q] = bx[q]; }
    __syncthreads();

    if (warp == 0) {
        float fv[5]; int fx[5];
#pragma unroll
        for (int q = 0; q < 5; ++q) { fv[q] = -__int_as_float(0x7f800000); fx[q] = 0x7fffffff; }
#pragma unroll
        for (int w = 0; w < 8; ++w)
#pragma unroll
            for (int q = 0; q < 5; ++q)
                top5_insert(sv[w][lane][q], si[w][lane][q], fv, fx);
#pragma unroll
        for (int q = 0; q < 5; ++q) g_nbr[row * KNN5 + q] = fx[q] < N ? fx[q] : 0;
    }
}

// ---------------- persistent mean-field iteration ---------------------------
// grid 148 x 512; unary + neighbor indices hoisted into registers
__global__ void __launch_bounds__(IT_THREADS) k_iterate(float* __restrict__ dout) {
    __shared__ float sE[IT_WARPS];
    __shared__ float sEbc;
    const int tid  = threadIdx.x;
    const int lane = tid & 31, wib = tid >> 5;
    const int warpG = blockIdx.x * IT_WARPS + wib;
    const int nW = NB_IT * IT_WARPS;   // 2368

    int nr = 0, rows[ROWS_MAX];
    for (int rr = warpG; rr < N; rr += nW) rows[nr++] = rr;
    float u0[ROWS_MAX], u1[ROWS_MAX];
    int   nb[ROWS_MAX][KNN5];
    for (int k = 0; k < nr; ++k) {
        u0[k] = g_unary[rows[k] * NC + lane];
        u1[k] = g_unary[rows[k] * NC + 32 + lane];
#pragma unroll
        for (int n = 0; n < KNN5; ++n) nb[k][n] = g_nbr[rows[k] * KNN5 + n];
    }

    float Eprev = __int_as_float(0x7f800000);
    int finalBuf = -1;

    for (int it = 0; it < MAXIT; ++it) {
        const float* __restrict__ Yin  = g_Ybuf[it & 1];
        float* __restrict__ Yout = g_Ybuf[(it + 1) & 1];
        float myE = 0.f;
        for (int k = 0; k < nr; ++k) {
            const int rr = rows[k];
            float pw0 = 0.f, pw1 = 0.f;
#pragma unroll
            for (int n = 0; n < KNN5; ++n) {
                const float* yr = Yin + (size_t)nb[k][n] * NC;
                pw0 += yr[lane];
                pw1 += yr[lane + 32];
            }
            float x0 = pw0 - u0[k], x1 = pw1 - u1[k];
            float m = fmaxf(x0, x1);
#pragma unroll
            for (int o = 16; o > 0; o >>= 1) m = fmaxf(m, __shfl_xor_sync(0xffffffffu, m, o));
            float e0 = __expf(x0 - m), e1 = __expf(x1 - m);
            float s = e0 + e1;
#pragma unroll
            for (int o = 16; o > 0; o >>= 1) s += __shfl_xor_sync(0xffffffffu, s, o);
            float inv = 1.0f / s;
            float y0 = e0 * inv, y1 = e1 * inv;
            Yout[rr * NC + lane]      = y0;
            Yout[rr * NC + 32 + lane] = y1;
            float ls = __logf(s);
            myE += y0 * (u0[k] - pw0 + (x0 - m - ls))
                 + y1 * (u1[k] - pw1 + (x1 - m - ls));
        }
#pragma unroll
        for (int o = 16; o > 0; o >>= 1) myE += __shfl_xor_sync(0xffffffffu, myE, o);
        if (lane == 0) sE[wib] = myE;
        __syncthreads();
        if (tid == 0) {
            float e = 0.f;
#pragma unroll
            for (int w = 0; w < IT_WARPS; ++w) e += sE[w];
            g_partE[it & 1][blockIdx.x] = e;
        }
        gridBarrier();
        // warp 0 computes global E in a fixed (block-uniform, deterministic) order
        if (wib == 0) {
            const float* pe = g_partE[it & 1];
            float e = pe[lane] + pe[lane + 32] + pe[lane + 64] + pe[lane + 96];
            if (lane < NB_IT - 128) e += pe[lane + 128];
#pragma unroll
            for (int o = 16; o > 0; o >>= 1) e += __shfl_xor_sync(0xffffffffu, e, o);
            if (lane == 0) sEbc = e;
        }
        __syncthreads();
        float E = sEbc;
        bool conv = (it > 1) && (fabsf(E - Eprev) <= 1e-8f * fabsf(Eprev));
        Eprev = E;
        if (conv) { finalBuf = (it + 1) & 1; break; }
    }
    if (finalBuf < 0) finalBuf = MAXIT & 1;
    const float* __restrict__ Yf = g_Ybuf[finalBuf];
    for (int k = 0; k < nr; ++k) {
        const int rr = rows[k];
        dout[rr * NC + lane]      = Yf[rr * NC + lane];
        dout[rr * NC + 32 + lane] = Yf[rr * NC + 32 + lane];
    }
}

// ---------------- launch -----------------------------------------------------
extern "C" void kernel_launch(void* const* d_in, const int* in_sizes, int n_in,
                              void* d_out, int out_size) {
    const float* scores;
    const float* feats;
    if (in_sizes[0] == N * NC) { scores = (const float*)d_in[0]; feats = (const float*)d_in[1]; }
    else                       { scores = (const float*)d_in[1]; feats = (const float*)d_in[0]; }
    float* out = (float*)d_out;

    const int gram_smem = 65536;
    cudaFuncSetAttribute(k_gram_mma, cudaFuncAttributeMaxDynamicSharedMemorySize, gram_smem);

    k_prep_unary<<<N / 8, 256>>>(scores);
    k_prep_feats<<<N, 256>>>(feats);
    k_gram_mma<<<NBI * (NBI + 1) / 2, 256, gram_smem>>>();
    k_merge<<<N / 32, 256>>>();
    k_iterate<<<NB_IT, IT_THREADS>>>(out);
}

// round 6
// speedup vs baseline: 2.2438x; 1.0023x over previous
#include <cuda_runtime.h>
#include <cuda_bf16.h>
#include <math.h>
#include <stdint.h>

#define N      8192
#define D      256
#define NC     64
#define KNN5   5
#define TI     128
#define KD     768          // split-bf16 expanded K: [h,l,h] x [h,h,l]
#define KC     64           // bf16 per smem stage (128 B/row)
#define NSTG   (KD/KC)      // 12
#define NBI    (N/TI)       // 64 block-rows
#define CAND   (NBI*KNN5)   // 320 candidates per row
#define NB_IT  148
#define IT_THREADS 512
#define IT_WARPS   16
#define ROWS_MAX   4        // ceil(8192 / (148*16)) = 4
#define MAXIT  100
#define LAM    1.0f

// ---------------- scratch ----------------------------------------------------
__device__ __nv_bfloat16 g_A[(size_t)N * KD];   // [h, l, h]
__device__ __nv_bfloat16 g_B[(size_t)N * KD];   // [h, h, l]
__device__ float g_unary[N * NC];
__device__ float g_Ybuf[2][N * NC];
__device__ float g_candV[(size_t)CAND * N];     // transposed: [slot][row]
__device__ int   g_candI[(size_t)CAND * N];
__device__ int   g_nbr[N * KNN5];
__device__ uint64_t g_slotE[(size_t)MAXIT * NB_IT];  // {flag<<32 | E bits}
__device__ uint64_t g_bcastE[MAXIT];

// ---------------- PTX helpers ------------------------------------------------
__device__ __forceinline__ uint32_t smem_u32(const void* p) {
    uint32_t a;
    asm("{ .reg .u64 t; cvta.to.shared.u64 t, %1; cvt.u32.u64 %0, t; }" : "=r"(a) : "l"(p));
    return a;
}
#define SWZ128(o) ((o) ^ (((o) >> 3) & 0x70))
#define CP_ASYNC16(dst, src) \
    asm volatile("cp.async.cg.shared.global [%0], [%1], 16;" :: "r"(dst), "l"(src) : "memory")
#define CP_COMMIT() asm volatile("cp.async.commit_group;" ::: "memory")
#define CP_WAIT(n)  asm volatile("cp.async.wait_group %0;" :: "n"(n) : "memory")
#define LDSM_X4(r0,r1,r2,r3, a) \
    asm volatile("ldmatrix.sync.aligned.m8n8.x4.shared.b16 {%0,%1,%2,%3}, [%4];" \
        : "=r"(r0),"=r"(r1),"=r"(r2),"=r"(r3) : "r"(a))
#define LDSM_X2(r0,r1, a) \
    asm volatile("ldmatrix.sync.aligned.m8n8.x2.shared.b16 {%0,%1}, [%2];" \
        : "=r"(r0),"=r"(r1) : "r"(a))
#define MMA16816(d, a, b) \
    asm volatile("mma.sync.aligned.m16n8k16.row.col.f32.bf16.bf16.f32 " \
        "{%0,%1,%2,%3}, {%4,%5,%6,%7}, {%8,%9}, {%0,%1,%2,%3};" \
        : "+f"((d)[0]),"+f"((d)[1]),"+f"((d)[2]),"+f"((d)[3]) \
        : "r"((a)[0]),"r"((a)[1]),"r"((a)[2]),"r"((a)[3]), "r"((b)[0]),"r"((b)[1]))

__device__ __forceinline__ void st_rel64(uint64_t* p, uint64_t v) {
    asm volatile("st.release.gpu.global.b64 [%0], %1;" :: "l"(p), "l"(v) : "memory");
}
__device__ __forceinline__ uint64_t ld_acq64(const uint64_t* p) {
    uint64_t v;
    asm volatile("ld.acquire.gpu.global.b64 %0, [%1];" : "=l"(v) : "l"(p) : "memory");
    return v;
}

// ---------------- misc helpers ----------------------------------------------
__device__ __forceinline__ void top5_insert(float v, int j, float bv[5], int bi[5]) {
    if (v > bv[4] || (v == bv[4] && j < bi[4])) {
        bv[4] = v; bi[4] = j;
#pragma unroll
        for (int s = 4; s > 0; --s) {
            if (bv[s] > bv[s-1] || (bv[s] == bv[s-1] && bi[s] < bi[s-1])) {
                float tv = bv[s]; bv[s] = bv[s-1]; bv[s-1] = tv;
                int   tj = bi[s]; bi[s] = bi[s-1]; bi[s-1] = tj;
            }
        }
    }
}

// ---------------- reset sync slots (graph-replay safe) -----------------------
__global__ void k_reset() {
    int i = blockIdx.x * 256 + threadIdx.x;
    if (i < MAXIT * NB_IT) g_slotE[i] = 0ull;
    if (i < MAXIT) g_bcastE[i] = 0ull;
}

// ---------------- prep: unary + Y0 ------------------------------------------
__global__ void k_prep_unary(const float* __restrict__ scores) {
    int wib = threadIdx.x >> 5, lane = threadIdx.x & 31;
    int r = blockIdx.x * 8 + wib;
    const float* s = scores + (size_t)r * NC;
    float u0 = -logf(s[lane]      + 1e-10f);
    float u1 = -logf(s[lane + 32] + 1e-10f);
    g_unary[r * NC + lane]      = u0;
    g_unary[r * NC + 32 + lane] = u1;
    float x0 = -u0, x1 = -u1;
    float m = fmaxf(x0, x1);
#pragma unroll
    for (int o = 16; o > 0; o >>= 1) m = fmaxf(m, __shfl_xor_sync(0xffffffffu, m, o));
    float e0 = __expf(x0 - m), e1 = __expf(x1 - m);
    float t = e0 + e1;
#pragma unroll
    for (int o = 16; o > 0; o >>= 1) t += __shfl_xor_sync(0xffffffffu, t, o);
    float inv = 1.0f / t;
    g_Ybuf[0][r * NC + lane]      = e0 * inv;
    g_Ybuf[0][r * NC + 32 + lane] = e1 * inv;
}

// ---------------- prep: normalize + split into bf16 hi/lo --------------------
__global__ void k_prep_feats(const float* __restrict__ feats) {
    __shared__ float red[8];
    __shared__ float nrmsh;
    int r = blockIdx.x, k = threadIdx.x;
    int lane = k & 31, w = k >> 5;
    float v = feats[(size_t)r * D + k];
    float s = v * v;
#pragma unroll
    for (int o = 16; o > 0; o >>= 1) s += __shfl_xor_sync(0xffffffffu, s, o);
    if (lane == 0) red[w] = s;
    __syncthreads();
    if (k == 0) {
        float t = 0.f;
#pragma unroll
        for (int i = 0; i < 8; ++i) t += red[i];
        nrmsh = sqrtf(t);
    }
    __syncthreads();
    float f = v / fmaxf(nrmsh, 1e-12f);
    __nv_bfloat16 h = __float2bfloat16(f);
    __nv_bfloat16 l = __float2bfloat16(f - __bfloat162float(h));
    size_t base = (size_t)r * KD;
    g_A[base + k]       = h;
    g_A[base + 256 + k] = l;
    g_A[base + 512 + k] = h;
    g_B[base + k]       = h;
    g_B[base + 256 + k] = h;
    g_B[base + 512 + k] = l;
}

// ---------------- HMMA Gram, upper-triangle tiles, fused dual top-5 ----------
__global__ void __launch_bounds__(256) k_gram_mma() {
    extern __shared__ char smem[];
    float* Cs = (float*)smem;                 // [64][129] overlay for epilogue
    const uint32_t sb = smem_u32(smem);
    const int tid = threadIdx.x;
    const int lane = tid & 31, warp = tid >> 5;
    const int wm = warp >> 2, wn = warp & 3;  // 2 x 4 warp grid

    int bi = 0, rem = blockIdx.x;
    while (rem >= NBI - bi) { rem -= NBI - bi; ++bi; }
    const int bj = bi + rem;
    const int ib = bi * TI, jb = bj * TI;

    float acc[4][4][4];
#pragma unroll
    for (int mf = 0; mf < 4; ++mf)
#pragma unroll
        for (int nf = 0; nf < 4; ++nf)
#pragma unroll
            for (int q = 0; q < 4; ++q) acc[mf][nf][q] = 0.f;

    const char* gA = (const char*)g_A;
    const char* gB = (const char*)g_B;

#define LOAD_STAGE(sidx, buf) do {                                              \
        int _s = (sidx); uint32_t _b = (uint32_t)(buf);                         \
        _Pragma("unroll")                                                       \
        for (int t = 0; t < 4; ++t) {                                           \
            int e = tid + t * 256;                                              \
            int row = e >> 3, ch = e & 7;                                       \
            uint32_t off = SWZ128((uint32_t)(row * 128 + ch * 16));             \
            CP_ASYNC16(sb + _b * 16384u + off,                                  \
                gA + ((size_t)(ib + row) * KD + (size_t)_s * KC) * 2 + ch * 16);\
            CP_ASYNC16(sb + 32768u + _b * 16384u + off,                         \
                gB + ((size_t)(jb + row) * KD + (size_t)_s * KC) * 2 + ch * 16);\
        }                                                                       \
        CP_COMMIT();                                                            \
    } while (0)

    LOAD_STAGE(0, 0);

    for (int s = 0; s < NSTG; ++s) {
        if (s + 1 < NSTG) { LOAD_STAGE(s + 1, (s + 1) & 1); CP_WAIT(1); }
        else              { CP_WAIT(0); }
        __syncthreads();

        const uint32_t aS = sb + (uint32_t)(s & 1) * 16384u;
        const uint32_t bS = sb + 32768u + (uint32_t)(s & 1) * 16384u;
#pragma unroll
        for (int kk = 0; kk < 4; ++kk) {
            uint32_t a[4][4], b[4][2];
#pragma unroll
            for (int mf = 0; mf < 4; ++mf) {
                int row = wm * 64 + mf * 16 + (lane & 15);
                uint32_t kb = kk * 32 + ((lane >> 4) << 4);
                LDSM_X4(a[mf][0], a[mf][1], a[mf][2], a[mf][3], aS + SWZ128((uint32_t)(row * 128) + kb));
            }
#pragma unroll
            for (int nf = 0; nf < 4; ++nf) {
                int nrow = wn * 32 + nf * 8 + (lane & 7);
                uint32_t kb = kk * 32 + (((lane >> 3) & 1) << 4);
                LDSM_X2(b[nf][0], b[nf][1], bS + SWZ128((uint32_t)(nrow * 128) + kb));
            }
#pragma unroll
            for (int mf = 0; mf < 4; ++mf)
#pragma unroll
                for (int nf = 0; nf < 4; ++nf)
                    MMA16816(acc[mf][nf], a[mf], b[nf]);
        }
        __syncthreads();
    }

    float bvC[5]; int biC[5];
#pragma unroll
    for (int q = 0; q < 5; ++q) { bvC[q] = -__int_as_float(0x7f800000); biC[q] = 0x7fffffff; }

#pragma unroll
    for (int h = 0; h < 2; ++h) {
        __syncthreads();
        if (wm == h) {
#pragma unroll
            for (int mf = 0; mf < 4; ++mf)
#pragma unroll
                for (int nf = 0; nf < 4; ++nf) {
                    int r0 = mf * 16 + (lane >> 2);
                    int c0 = wn * 32 + nf * 8 + 2 * (lane & 3);
                    Cs[r0 * 129 + c0]           = acc[mf][nf][0];
                    Cs[r0 * 129 + c0 + 1]       = acc[mf][nf][1];
                    Cs[(r0 + 8) * 129 + c0]     = acc[mf][nf][2];
                    Cs[(r0 + 8) * 129 + c0 + 1] = acc[mf][nf][3];
                }
        }
        __syncthreads();
        if (tid < 64) {
            int gi = ib + h * 64 + tid;
            float bv[5]; int bx[5];
#pragma unroll
            for (int q = 0; q < 5; ++q) { bv[q] = -__int_as_float(0x7f800000); bx[q] = 0x7fffffff; }
            for (int c = 0; c < TI; ++c) {
                int gj = jb + c;
                if (gj != gi) top5_insert(Cs[tid * 129 + c], gj, bv, bx);
            }
#pragma unroll
            for (int q = 0; q < 5; ++q) {
                g_candV[(size_t)(bj * KNN5 + q) * N + gi] = bv[q];
                g_candI[(size_t)(bj * KNN5 + q) * N + gi] = bx[q];
            }
        }
        if (bi != bj && tid < 128) {
            for (int r = 0; r < 64; ++r)
                top5_insert(Cs[r * 129 + tid], ib + h * 64 + r, bvC, biC);
        }
    }
    if (bi != bj && tid < 128) {
        int gj = jb + tid;
#pragma unroll
        for (int q = 0; q < 5; ++q) {
            g_candV[(size_t)(bi * KNN5 + q) * N + gj] = bvC[q];
            g_candI[(size_t)(bi * KNN5 + q) * N + gj] = biC[q];
        }
    }
#undef LOAD_STAGE
}

// ---------------- merge: 256 blocks, warp w scans slot group w for 32 rows ---
__global__ void __launch_bounds__(256) k_merge() {
    __shared__ float sv[8][32][5];
    __shared__ int   si[8][32][5];
    const int warp = threadIdx.x >> 5, lane = threadIdx.x & 31;
    const int row = blockIdx.x * 32 + lane;

    float bv[5]; int bx[5];
#pragma unroll
    for (int q = 0; q < 5; ++q) { bv[q] = -__int_as_float(0x7f800000); bx[q] = 0x7fffffff; }
    const int c0 = warp * (CAND / 8);
    for (int c = c0; c < c0 + CAND / 8; ++c)
        top5_insert(g_candV[(size_t)c * N + row], g_candI[(size_t)c * N + row], bv, bx);
#pragma unroll
    for (int q = 0; q < 5; ++q) { sv[warp][lane][q] = bv[q]; si[warp][lane][q] = bx[q]; }
    __syncthreads();

    if (warp == 0) {
        float fv[5]; int fx[5];
#pragma unroll
        for (int q = 0; q < 5; ++q) { fv[q] = -__int_as_float(0x7f800000); fx[q] = 0x7fffffff; }
#pragma unroll
        for (int w = 0; w < 8; ++w)
#pragma unroll
            for (int q = 0; q < 5; ++q)
                top5_insert(sv[w][lane][q], si[w][lane][q], fv, fx);
#pragma unroll
        for (int q = 0; q < 5; ++q) g_nbr[row * KNN5 + q] = fx[q] < N ? fx[q] : 0;
    }
}

// ---------------- persistent mean-field iteration (flag-based global sync) ---
__global__ void __launch_bounds__(IT_THREADS) k_iterate(float* __restrict__ dout) {
    __shared__ float sE[IT_WARPS];
    __shared__ float sEarr[NB_IT];
    __shared__ float sEbc;
    const int tid  = threadIdx.x;
    const int lane = tid & 31, wib = tid >> 5;
    const int warpG = blockIdx.x * IT_WARPS + wib;
    const int nW = NB_IT * IT_WARPS;   // 2368

    int nr = 0, rows[ROWS_MAX];
    float u0[ROWS_MAX], u1[ROWS_MAX];
    int   nb[ROWS_MAX][KNN5];
#pragma unroll
    for (int k = 0; k < ROWS_MAX; ++k) {
        rows[k] = 0; u0[k] = 0.f; u1[k] = 0.f;
#pragma unroll
        for (int n = 0; n < KNN5; ++n) nb[k][n] = 0;
    }
    for (int rr = warpG; rr < N; rr += nW) rows[nr++] = rr;
    for (int k = 0; k < nr; ++k) {
        u0[k] = g_unary[rows[k] * NC + lane];
        u1[k] = g_unary[rows[k] * NC + 32 + lane];
#pragma unroll
        for (int n = 0; n < KNN5; ++n) nb[k][n] = g_nbr[rows[k] * KNN5 + n];
    }

    float Eprev = __int_as_float(0x7f800000);
    int finalBuf = -1;

    for (int it = 0; it < MAXIT; ++it) {
        const float* __restrict__ Yin  = g_Ybuf[it & 1];
        float* __restrict__ Yout = g_Ybuf[(it + 1) & 1];

        // batched gathers across all rows (max MLP)
        float pw0[ROWS_MAX], pw1[ROWS_MAX];
#pragma unroll
        for (int k = 0; k < ROWS_MAX; ++k) {
            float a0 = 0.f, a1 = 0.f;
#pragma unroll
            for (int n = 0; n < KNN5; ++n) {
                const float* yr = Yin + (size_t)nb[k][n] * NC;
                a0 += yr[lane];
                a1 += yr[lane + 32];
            }
            pw0[k] = a0; pw1[k] = a1;
        }
        // interleaved softmax chains across rows
        float x0[ROWS_MAX], x1[ROWS_MAX], m[ROWS_MAX], ssum[ROWS_MAX];
        float e0[ROWS_MAX], e1[ROWS_MAX];
#pragma unroll
        for (int k = 0; k < ROWS_MAX; ++k) {
            x0[k] = pw0[k] - u0[k]; x1[k] = pw1[k] - u1[k];
            m[k] = fmaxf(x0[k], x1[k]);
        }
#pragma unroll
        for (int o = 16; o > 0; o >>= 1)
#pragma unroll
            for (int k = 0; k < ROWS_MAX; ++k)
                m[k] = fmaxf(m[k], __shfl_xor_sync(0xffffffffu, m[k], o));
#pragma unroll
        for (int k = 0; k < ROWS_MAX; ++k) {
            e0[k] = __expf(x0[k] - m[k]); e1[k] = __expf(x1[k] - m[k]);
            ssum[k] = e0[k] + e1[k];
        }
#pragma unroll
        for (int o = 16; o > 0; o >>= 1)
#pragma unroll
            for (int k = 0; k < ROWS_MAX; ++k)
                ssum[k] += __shfl_xor_sync(0xffffffffu, ssum[k], o);

        float myE = 0.f;
#pragma unroll
        for (int k = 0; k < ROWS_MAX; ++k) {
            if (k < nr) {
                float inv = 1.0f / ssum[k];
                float y0 = e0[k] * inv, y1 = e1[k] * inv;
                const int rr = rows[k];
                Yout[rr * NC + lane]      = y0;
                Yout[rr * NC + 32 + lane] = y1;
                float ls = __logf(ssum[k]);
                myE += y0 * (u0[k] - pw0[k] + (x0[k] - m[k] - ls))
                     + y1 * (u1[k] - pw1[k] + (x1[k] - m[k] - ls));
            }
        }
#pragma unroll
        for (int o = 16; o > 0; o >>= 1) myE += __shfl_xor_sync(0xffffffffu, myE, o);
        if (lane == 0) sE[wib] = myE;
        __syncthreads();
        if (tid == 0) {
            float e = 0.f;
#pragma unroll
            for (int w = 0; w < IT_WARPS; ++w) e += sE[w];
            st_rel64(&g_slotE[(size_t)it * NB_IT + blockIdx.x],
                     ((uint64_t)1 << 32) | (uint64_t)__float_as_uint(e));
        }
        // global sync + energy broadcast via release/acquire flags
        if (blockIdx.x == 0) {
            if (tid < NB_IT) {
                uint64_t v;
                do { v = ld_acq64(&g_slotE[(size_t)it * NB_IT + tid]); } while (!(v >> 32));
                sEarr[tid] = __uint_as_float((uint32_t)v);
            }
            __syncthreads();
            if (wib == 0) {
                const float* pe = sEarr;
                float e = pe[lane] + pe[lane + 32] + pe[lane + 64] + pe[lane + 96];
                if (lane < NB_IT - 128) e += pe[lane + 128];
#pragma unroll
                for (int o = 16; o > 0; o >>= 1) e += __shfl_xor_sync(0xffffffffu, e, o);
                if (lane == 0) {
                    sEbc = e;
                    st_rel64(&g_bcastE[it], ((uint64_t)1 << 32) | (uint64_t)__float_as_uint(e));
                }
            }
            __syncthreads();
        } else {
            if (tid == 0) {
                uint64_t v;
                do { v = ld_acq64(&g_bcastE[it]); } while (!(v >> 32));
                sEbc = __uint_as_float((uint32_t)v);
            }
            __syncthreads();
        }
        float E = sEbc;
        bool conv = (it > 1) && (fabsf(E - Eprev) <= 1e-8f * fabsf(Eprev));
        Eprev = E;
        if (conv) { finalBuf = (it + 1) & 1; break; }
        __syncthreads();   // protect sEbc/sE reuse next iteration
    }
    if (finalBuf < 0) finalBuf = MAXIT & 1;
    const float* __restrict__ Yf = g_Ybuf[finalBuf];
    for (int k = 0; k < nr; ++k) {
        const int rr = rows[k];
        dout[rr * NC + lane]      = Yf[rr * NC + lane];
        dout[rr * NC + 32 + lane] = Yf[rr * NC + 32 + lane];
    }
}

// ---------------- launch -----------------------------------------------------
extern "C" void kernel_launch(void* const* d_in, const int* in_sizes, int n_in,
                              void* d_out, int out_size) {
    const float* scores;
    const float* feats;
    if (in_sizes[0] == N * NC) { scores = (const float*)d_in[0]; feats = (const float*)d_in[1]; }
    else                       { scores = (const float*)d_in[1]; feats = (const float*)d_in[0]; }
    float* out = (float*)d_out;

    const int gram_smem = 65536;
    cudaFuncSetAttribute(k_gram_mma, cudaFuncAttributeMaxDynamicSharedMemorySize, gram_smem);

    k_reset<<<(MAXIT * NB_IT + 255) / 256, 256>>>();
    k_prep_unary<<<N / 8, 256>>>(scores);
    k_prep_feats<<<N, 256>>>(feats);
    k_gram_mma<<<NBI * (NBI + 1) / 2, 256, gram_smem>>>();
    k_merge<<<N / 32, 256>>>();
    k_iterate<<<NB_IT, IT_THREADS>>>(out);
}